// round 17
// baseline (speedup 1.0000x reference)
#include <cuda_runtime.h>
#include <cuda_fp16.h>

// HashEmbedding: out[t, d] = sum_{h=0..3} weight_table[x[t,h] + 513*h] * emb_table[x[t,h]>>1][d]
// x is int32.
// R17: R13 mainloop VERBATIM (proven floor: smem fp16 table via bulk-copy,
// LDS.64 gathers, half2 weights, HFMA2, pair-ILP, coalesced f32 stores) + PDL:
// the convert kernel triggers launch_dependents after its stores; the main
// kernel is launched with ProgrammaticStreamSerialization and only executes
// griddepcontrol.wait right before the table bulk-copies. Launch overhead,
// mbarrier init and first x-index loads overlap the convert kernel.

#define NUM_HASHES 4
#define D 256
#define W_TABLE 2052           // 512*4 + 4
#define EMB_ROWS 256
#define BLOCK_THREADS 1024
#define WARPS_PER_BLOCK (BLOCK_THREADS / 32)
#define GRID_X 148

#define W_BYTES   (W_TABLE * 4)          // 8208 (half2 per entry)
#define EMB_BYTES (EMB_ROWS * D * 2)     // 131072

// smem byte offsets
#define OFF_W     0                      // half2[2052]
#define OFF_MBAR  8208
#define OFF_EMB   8320                   // 128-aligned
#define SMEM_BYTES (OFF_EMB + EMB_BYTES)

// Pre-converted tables (filled by convert kernel each replay).
__device__ __align__(16) __half2 g_wh2[W_TABLE];
__device__ __align__(16) __half2 g_emb_h2[EMB_ROWS * D / 2];

__global__ void convert_tables_kernel(const float* __restrict__ weight_table,
                                      const float* __restrict__ emb_table)
{
    const int i = blockIdx.x * blockDim.x + threadIdx.x;
    if (i < W_TABLE) {
        g_wh2[i] = __float2half2_rn(weight_table[i]);   // duplicated lanes
    }
    if (i < EMB_ROWS * D / 2) {
        const float2 v = *reinterpret_cast<const float2*>(emb_table + i * 2);
        g_emb_h2[i] = __floats2half2_rn(v.x, v.y);
    }
    // PDL: allow the dependent (main) grid to launch; writes above are
    // guaranteed visible to it after its griddepcontrol.wait.
    asm volatile("griddepcontrol.launch_dependents;");
}

__global__ __launch_bounds__(BLOCK_THREADS, 1)
void hash_embedding_kernel(const int* __restrict__ x,
                           float* __restrict__ out,
                           int ntok)
{
    extern __shared__ char smem[];
    const __half2* s_wh  = reinterpret_cast<const __half2*>(smem + OFF_W);
    const char*    s_emb = smem + OFF_EMB;   // [256 rows][256 halves] = 512 B/row

    const int tid = threadIdx.x;

    unsigned int smem_base;
    asm("{ .reg .u64 t; cvta.to.shared.u64 t, %1; cvt.u32.u64 %0, t; }"
        : "=r"(smem_base) : "l"(smem));

    // ---- async bulk-load both pre-converted tables (waits on PDL first) ----
    if (tid == 0) {
        asm volatile("mbarrier.init.shared.b64 [%0], 1;"
                     :: "r"(smem_base + OFF_MBAR) : "memory");
        asm volatile("fence.proxy.async.shared::cta;" ::: "memory");
        asm volatile("mbarrier.arrive.expect_tx.shared.b64 _, [%0], %1;"
                     :: "r"(smem_base + OFF_MBAR),
                        "r"((unsigned)(W_BYTES + EMB_BYTES)) : "memory");
        // PDL: block until the convert kernel's writes are visible.
        asm volatile("griddepcontrol.wait;" ::: "memory");
        asm volatile(
            "cp.async.bulk.shared::cta.global.mbarrier::complete_tx::bytes "
            "[%0], [%1], %2, [%3];"
            :: "r"(smem_base + OFF_W), "l"(g_wh2),
               "r"((unsigned)W_BYTES), "r"(smem_base + OFF_MBAR) : "memory");
        asm volatile(
            "cp.async.bulk.shared::cta.global.mbarrier::complete_tx::bytes "
            "[%0], [%1], %2, [%3];"
            :: "r"(smem_base + OFF_EMB), "l"(g_emb_h2),
               "r"((unsigned)EMB_BYTES), "r"(smem_base + OFF_MBAR) : "memory");
    }
    __syncthreads();   // mbarrier init visible to all before waiting

    const int lane = tid & 31;
    const int gw   = blockIdx.x * WARPS_PER_BLOCK + (tid >> 5);
    const int nw   = GRID_X * WARPS_PER_BLOCK;     // 4736 warps

    const int offA = lane * 8;          // cols [lane*4 .. lane*4+3]   (8 B fp16)
    const int offB = 256 + lane * 8;    // cols [128+lane*4 .. +3]

    const int npairs = ntok >> 1;       // 32768

    int p = gw;                         // always < npairs (4736 < 32768)

    // Hoisted first-pair index loads: overlap x latency with the bulk copy.
    int4 xi0 = *reinterpret_cast<const int4*>(x + (long long)(2 * p)     * NUM_HASHES);
    int4 xi1 = *reinterpret_cast<const int4*>(x + (long long)(2 * p + 1) * NUM_HASHES);

    // wait for the table bulk copy (phase 0)
    {
        unsigned int mbar = smem_base + OFF_MBAR;
        unsigned int done;
        asm volatile(
            "{\n\t.reg .pred p;\n\t"
            "mbarrier.try_wait.parity.acquire.cta.shared::cta.b64 p, [%1], 0;\n\t"
            "selp.b32 %0, 1, 0, p;\n\t}"
            : "=r"(done) : "r"(mbar) : "memory");
        if (!done) {
            asm volatile(
                "{\n\t.reg .pred P1;\n\t"
                "WL_%=:\n\t"
                "mbarrier.try_wait.parity.acquire.cta.shared::cta.b64 P1, [%0], 0, 0x989680;\n\t"
                "@P1 bra.uni WD_%=;\n\t"
                "bra.uni WL_%=;\n\t"
                "WD_%=:\n\t}"
                :: "r"(mbar) : "memory");
        }
    }

    #pragma unroll 1
    for (; p < npairs; p += nw) {
        const int pn = (p + nw < npairs) ? (p + nw) : p;
        const int4 xn0 = *reinterpret_cast<const int4*>(x + (long long)(2 * pn)     * NUM_HASHES);
        const int4 xn1 = *reinterpret_cast<const int4*>(x + (long long)(2 * pn + 1) * NUM_HASHES);

        // per-sample weights as duplicated half2 (LDS.32 broadcast, no cvt)
        const __half2 u0 = s_wh[xi0.x];
        const __half2 u1 = s_wh[xi0.y + 513];
        const __half2 u2 = s_wh[xi0.z + 1026];
        const __half2 u3 = s_wh[xi0.w + 1539];
        const __half2 v0 = s_wh[xi1.x];
        const __half2 v1 = s_wh[xi1.y + 513];
        const __half2 v2 = s_wh[xi1.z + 1026];
        const __half2 v3 = s_wh[xi1.w + 1539];

        // fp16 row bases (idx = x >> 1; 512 B per row)
        const char* p00 = s_emb + ((xi0.x >> 1) << 9);
        const char* p01 = s_emb + ((xi0.y >> 1) << 9);
        const char* p02 = s_emb + ((xi0.z >> 1) << 9);
        const char* p03 = s_emb + ((xi0.w >> 1) << 9);
        const char* p10 = s_emb + ((xi1.x >> 1) << 9);
        const char* p11 = s_emb + ((xi1.y >> 1) << 9);
        const char* p12 = s_emb + ((xi1.z >> 1) << 9);
        const char* p13 = s_emb + ((xi1.w >> 1) << 9);

        // batch all 16 gather loads (LDS.64, conflict-free)
        uint2 gA0 = *reinterpret_cast<const uint2*>(p00 + offA);
        uint2 gA1 = *reinterpret_cast<const uint2*>(p01 + offA);
        uint2 gA2 = *reinterpret_cast<const uint2*>(p02 + offA);
        uint2 gA3 = *reinterpret_cast<const uint2*>(p03 + offA);
        uint2 hA0 = *reinterpret_cast<const uint2*>(p10 + offA);
        uint2 hA1 = *reinterpret_cast<const uint2*>(p11 + offA);
        uint2 hA2 = *reinterpret_cast<const uint2*>(p12 + offA);
        uint2 hA3 = *reinterpret_cast<const uint2*>(p13 + offA);
        uint2 gB0 = *reinterpret_cast<const uint2*>(p00 + offB);
        uint2 gB1 = *reinterpret_cast<const uint2*>(p01 + offB);
        uint2 gB2 = *reinterpret_cast<const uint2*>(p02 + offB);
        uint2 gB3 = *reinterpret_cast<const uint2*>(p03 + offB);
        uint2 hB0 = *reinterpret_cast<const uint2*>(p10 + offB);
        uint2 hB1 = *reinterpret_cast<const uint2*>(p11 + offB);
        uint2 hB2 = *reinterpret_cast<const uint2*>(p12 + offB);
        uint2 hB3 = *reinterpret_cast<const uint2*>(p13 + offB);

        #define H2(u) (*reinterpret_cast<const __half2*>(&(u)))

        __half2 aAx = __hmul2(H2(gA0.x), u0);
        __half2 aAy = __hmul2(H2(gA0.y), u0);
        aAx = __hfma2(H2(gA1.x), u1, aAx);  aAy = __hfma2(H2(gA1.y), u1, aAy);
        aAx = __hfma2(H2(gA2.x), u2, aAx);  aAy = __hfma2(H2(gA2.y), u2, aAy);
        aAx = __hfma2(H2(gA3.x), u3, aAx);  aAy = __hfma2(H2(gA3.y), u3, aAy);

        __half2 aBx = __hmul2(H2(gB0.x), u0);
        __half2 aBy = __hmul2(H2(gB0.y), u0);
        aBx = __hfma2(H2(gB1.x), u1, aBx);  aBy = __hfma2(H2(gB1.y), u1, aBy);
        aBx = __hfma2(H2(gB2.x), u2, aBx);  aBy = __hfma2(H2(gB2.y), u2, aBy);
        aBx = __hfma2(H2(gB3.x), u3, aBx);  aBy = __hfma2(H2(gB3.y), u3, aBy);

        __half2 bAx = __hmul2(H2(hA0.x), v0);
        __half2 bAy = __hmul2(H2(hA0.y), v0);
        bAx = __hfma2(H2(hA1.x), v1, bAx);  bAy = __hfma2(H2(hA1.y), v1, bAy);
        bAx = __hfma2(H2(hA2.x), v2, bAx);  bAy = __hfma2(H2(hA2.y), v2, bAy);
        bAx = __hfma2(H2(hA3.x), v3, bAx);  bAy = __hfma2(H2(hA3.y), v3, bAy);

        __half2 bBx = __hmul2(H2(hB0.x), v0);
        __half2 bBy = __hmul2(H2(hB0.y), v0);
        bBx = __hfma2(H2(hB1.x), v1, bBx);  bBy = __hfma2(H2(hB1.y), v1, bBy);
        bBx = __hfma2(H2(hB2.x), v2, bBx);  bBy = __hfma2(H2(hB2.y), v2, bBy);
        bBx = __hfma2(H2(hB3.x), v3, bBx);  bBy = __hfma2(H2(hB3.y), v3, bBy);

        #undef H2

        const float2 fA0 = __half22float2(aAx), fA1 = __half22float2(aAy);
        const float2 fB0 = __half22float2(aBx), fB1 = __half22float2(aBy);
        const float2 gA  = __half22float2(bAx), gA1f = __half22float2(bAy);
        const float2 gB  = __half22float2(bBx), gB1f = __half22float2(bBy);

        // coalesced stores: lane L writes cols [L*4, L*4+4) of each 128-col half
        float* op = out + (long long)(2 * p) * D + lane * 4;
        *reinterpret_cast<float4*>(op)       = make_float4(fA0.x, fA0.y, fA1.x, fA1.y);
        *reinterpret_cast<float4*>(op + 128) = make_float4(fB0.x, fB0.y, fB1.x, fB1.y);
        *reinterpret_cast<float4*>(op + 256) = make_float4(gA.x,  gA.y,  gA1f.x, gA1f.y);
        *reinterpret_cast<float4*>(op + 384) = make_float4(gB.x,  gB.y,  gB1f.x, gB1f.y);

        xi0 = xn0;
        xi1 = xn1;
    }
}

extern "C" void kernel_launch(void* const* d_in, const int* in_sizes, int n_in,
                              void* d_out, int out_size)
{
    const int*   x            = (const int*)d_in[0];
    const float* weight_table = (const float*)d_in[1];
    const float* emb_table    = (const float*)d_in[2];
    float*       out          = (float*)d_out;

    const int ntok = in_sizes[0] / NUM_HASHES;   // 65536

    cudaFuncSetAttribute(hash_embedding_kernel,
                         cudaFuncAttributeMaxDynamicSharedMemorySize, SMEM_BYTES);

    // 1) convert kernel (primary)
    convert_tables_kernel<<<(EMB_ROWS * D / 2 + 255) / 256, 256>>>(weight_table, emb_table);

    // 2) main kernel launched with programmatic dependent launch: it comes up
    //    while the convert kernel drains, and blocks only at griddepcontrol.wait.
    cudaLaunchConfig_t cfg = {};
    cfg.gridDim  = dim3(GRID_X, 1, 1);
    cfg.blockDim = dim3(BLOCK_THREADS, 1, 1);
    cfg.dynamicSmemBytes = SMEM_BYTES;
    cfg.stream = 0;
    cudaLaunchAttribute attr[1];
    attr[0].id = cudaLaunchAttributeProgrammaticStreamSerialization;
    attr[0].val.programmaticStreamSerializationAllowed = 1;
    cfg.attrs = attr;
    cfg.numAttrs = 1;
    cudaLaunchKernelEx(&cfg, hash_embedding_kernel, x, out, ntok);
}